// round 13
// baseline (speedup 1.0000x reference)
#include <cuda_runtime.h>
#include <cuda_fp16.h>
#include <stdint.h>
#include <math.h>

// ---------------- problem constants ----------------
constexpr int B_   = 64;
constexpr int C_   = 3;
constexpr int HW_  = 512;
constexpr int P_   = 16;
constexpr int D_   = 256;    // token dim
constexpr int G_   = 32;     // GH = GW
constexpr int NP_  = 1024;
constexpr int T_   = 1025;   // tokens (NP+1)
constexpr int TH_  = 513;    // half-spectrum rows (0..512)
constexpr int TP_  = 1056;   // tokens padded to 32-multiple for mma K loop
constexpr int HID_ = 1024;
constexpr int L_   = 6;
constexpr int NC_  = 1000;
constexpr int KH_  = 129;    // half-spectrum columns (0..128)
constexpr int KN_  = 128;    // mma-handled spectrum columns (0..127)
constexpr int KC_  = 768;    // C*P*P
constexpr int M_   = B_ * T_; // 65600 rows

// dynamic-smem layout for double-buffered dftmma (units: halves)
constexpr int A_H     = 128 * 40;              // 5120
constexpr int B_H     = 32 * 136;              // 4352
constexpr int STG_H   = 2 * A_H + 2 * B_H;     // 18944 halves per stage
constexpr int OFF_ASL = A_H;                   // 5120
constexpr int OFF_BSH = 2 * A_H;               // 10240
constexpr int OFF_BSL = 2 * A_H + B_H;         // 14592
constexpr int SMEM_DFT_BYTES = 2 * STG_H * 2;  // 75776 bytes

// ---------------- scratch (device globals; no allocation) ----------------
__device__ float  g_t   [B_*T_*D_];        // residual stream
__device__ __half g_hh  [B_*T_*D_];        // LN output, fp16 hi
__device__ __half g_hl  [B_*T_*D_];        // LN output, fp16 lo
__device__ float  g_hc128[B_*TP_];         // dim-DFT Nyquist col (alternating sums)
__device__ __half g_hch [B_*TP_*KN_];      // Hc hi (pad token rows zero)
__device__ __half g_hcl [B_*TP_*KN_];      // Hc lo
__device__ __half g_hsh [B_*TP_*KN_];      // Hs hi
__device__ __half g_hsl [B_*TP_*KN_];      // Hs lo
__device__ float  g_U   [B_*TH_*KN_];      // token-DFT cosine part
__device__ __half g_mid16[B_*T_*HID_];
__device__ float  g_C1f [TH_*T_];          // fp32 C1 rows 0..512 (Nyquist MV)
__device__ __half g_C1h [TH_*TP_];         // split token-DFT matrices (pad cols zero)
__device__ __half g_C1l [TH_*TP_];
__device__ __half g_S1h [TH_*TP_];
__device__ __half g_S1l [TH_*TP_];
__device__ __half g_C2h [D_*KN_];          // split dim-DFT matrices
__device__ __half g_C2l [D_*KN_];
__device__ __half g_S2h [D_*KN_];
__device__ __half g_S2l [D_*KN_];
__device__ float  g_wT  [KC_*D_];
__device__ float  g_pool[B_*D_];
__device__ __half g_w1h [L_*D_*HID_];
__device__ __half g_w2h [L_*HID_*D_];

// ---------------- mma / cp.async helpers (spaces after braces: template-
// renderer safe) ----------------
__device__ __forceinline__ void ldsm_x4(uint32_t* r, uint32_t addr) {
    asm volatile("ldmatrix.sync.aligned.m8n8.x4.shared.b16 { %0, %1, %2, %3 }, [ %4 ];"
                 : "=r"(r[0]), "=r"(r[1]), "=r"(r[2]), "=r"(r[3]) : "r"(addr));
}
__device__ __forceinline__ void ldsm_x4_t(uint32_t* r, uint32_t addr) {
    asm volatile("ldmatrix.sync.aligned.m8n8.x4.trans.shared.b16 { %0, %1, %2, %3 }, [ %4 ];"
                 : "=r"(r[0]), "=r"(r[1]), "=r"(r[2]), "=r"(r[3]) : "r"(addr));
}
__device__ __forceinline__ void mma16816(float* d, const uint32_t* a, const uint32_t* b) {
    asm volatile("mma.sync.aligned.m16n8k16.row.col.f32.f16.f16.f32 "
                 "{ %0, %1, %2, %3 }, { %4, %5, %6, %7 }, { %8, %9 }, { %0, %1, %2, %3 };"
                 : "+f"(d[0]), "+f"(d[1]), "+f"(d[2]), "+f"(d[3])
                 : "r"(a[0]), "r"(a[1]), "r"(a[2]), "r"(a[3]), "r"(b[0]), "r"(b[1]));
}
__device__ __forceinline__ void split16(float x, __half& h, __half& l) {
    h = __float2half(x);
    l = __float2half(x - __half2float(h));
}
__device__ __forceinline__ void cpa16(uint32_t dst, const void* src) {
    asm volatile("cp.async.cg.shared.global [ %0 ], [ %1 ], 16;" :: "r"(dst), "l"(src));
}
__device__ __forceinline__ void cpa_commit() {
    asm volatile("cp.async.commit_group;");
}
template<int W>
__device__ __forceinline__ void cpa_wait() {
    asm volatile("cp.async.wait_group %0;" :: "n"(W));
}

// ---------------- init kernels ----------------
__global__ void k_init1f() {       // fp32 C1, rows 0..512
    int idx = blockIdx.x * blockDim.x + threadIdx.x;
    if (idx >= TH_ * T_) return;
    int k = idx / T_, n = idx % T_;
    int prod = (int)(((long long)k * n) % T_);
    g_C1f[idx] = cosf((float)(6.283185307179586 * (double)prod / (double)T_));
}

__global__ void k_init1s() {       // split fp16 C1/S1, rows 0..512, cols padded
    int idx = blockIdx.x * blockDim.x + threadIdx.x;
    if (idx >= TH_ * TP_) return;
    int k = idx / TP_, n = idx % TP_;
    float c = 0.f, s = 0.f;
    if (n < T_) {
        int prod = (int)(((long long)k * n) % T_);
        float ang = (float)(6.283185307179586 * (double)prod / (double)T_);
        sincosf(ang, &s, &c);
    }
    __half h, l;
    split16(c, h, l); g_C1h[idx] = h; g_C1l[idx] = l;
    split16(s, h, l); g_S1h[idx] = h; g_S1l[idx] = l;
}

__global__ void k_init2s() {       // split fp16 C2/S2, cols 0..127
    int idx = blockIdx.x * blockDim.x + threadIdx.x;
    if (idx >= D_ * KN_) return;
    int n2 = idx / KN_, k2 = idx % KN_;
    int prod = (n2 * k2) & (D_ - 1);
    float ang = (float)(6.283185307179586 * (double)prod / (double)D_);
    float s, c; sincosf(ang, &s, &c);
    __half h, l;
    split16(c, h, l); g_C2h[idx] = h; g_C2l[idx] = l;
    split16(s, h, l); g_S2h[idx] = h; g_S2l[idx] = l;
}

__global__ void k_twt(const float* __restrict__ w) {
    int idx = blockIdx.x * blockDim.x + threadIdx.x;
    if (idx >= KC_ * D_) return;
    int k = idx >> 8, d = idx & 255;
    g_wT[idx] = w[d * KC_ + k];
}

__global__ void k_cvtw(const float* __restrict__ w1, const float* __restrict__ w2) {
    int i = blockIdx.x * blockDim.x + threadIdx.x;
    if (i >= L_ * D_ * HID_) return;
    g_w1h[i] = __float2half(w1[i]);
    g_w2h[i] = __float2half(w2[i]);
}

__global__ void k_cls(const float* __restrict__ cls, const float* __restrict__ pos) {
    int idx = blockIdx.x * blockDim.x + threadIdx.x;
    int b = idx >> 8, d = idx & 255;
    g_t[(size_t)b * T_ * D_ + d] = cls[d] + pos[d];
}

// ---------------- patch-embed GEMM (fp32 SIMT) ----------------
__global__ void k_patch(const float* __restrict__ x, const float* __restrict__ cb,
                        const float* __restrict__ pos) {
    __shared__ float As[16][65];
    __shared__ float Bs[16][65];
    int tid = threadIdx.x;
    int tx = tid & 15, ty = tid >> 4;
    int m0 = blockIdx.y * 64, n0 = blockIdx.x * 64;
    float acc[4][4] = {};
    for (int k0 = 0; k0 < KC_; k0 += 16) {
        #pragma unroll
        for (int l = 0; l < 4; l++) {
            int idx = tid + l * 256;
            int k = idx & 15, m = idx >> 4;
            int r = m0 + m, kg = k0 + k;
            int b = r >> 10, patch = r & 1023;
            int gh = patch >> 5, gw = patch & 31;
            int c = kg >> 8, p = (kg >> 4) & 15, q = kg & 15;
            As[k][m] = x[(((size_t)(b * 3 + c) * 512) + gh * 16 + p) * 512 + gw * 16 + q];
        }
        #pragma unroll
        for (int l = 0; l < 4; l++) {
            int idx = tid + l * 256;
            int n = idx & 63, k = idx >> 6;
            Bs[k][n] = g_wT[(k0 + k) * D_ + n0 + n];
        }
        __syncthreads();
        #pragma unroll
        for (int kk = 0; kk < 16; kk++) {
            float ra[4], rb[4];
            #pragma unroll
            for (int i = 0; i < 4; i++) ra[i] = As[kk][ty * 4 + i];
            #pragma unroll
            for (int j = 0; j < 4; j++) rb[j] = Bs[kk][tx * 4 + j];
            #pragma unroll
            for (int i = 0; i < 4; i++)
                #pragma unroll
                for (int j = 0; j < 4; j++) acc[i][j] += ra[i] * rb[j];
        }
        __syncthreads();
    }
    #pragma unroll
    for (int i = 0; i < 4; i++) {
        int r = m0 + ty * 4 + i;
        int b = r >> 10, patch = r & 1023;
        size_t base = ((size_t)b * T_ + 1 + patch) * D_;
        #pragma unroll
        for (int j = 0; j < 4; j++) {
            int d = n0 + tx * 4 + j;
            g_t[base + d] = acc[i][j] + cb[d] + pos[(1 + patch) * D_ + d];
        }
    }
}

// ---------------- LayerNorm -> split fp16 (hi, lo) + Nyquist alt-sum --------
__global__ void k_ln(const float* __restrict__ s, const float* __restrict__ bb) {
    int row  = blockIdx.x * 8 + (threadIdx.x >> 5);
    int lane = threadIdx.x & 31;
    const float* x = g_t + (size_t)row * D_;
    float v[8]; float sum = 0.f;
    #pragma unroll
    for (int i = 0; i < 8; i++) { v[i] = x[lane + i * 32]; sum += v[i]; }
    #pragma unroll
    for (int o = 16; o > 0; o >>= 1) sum += __shfl_xor_sync(0xffffffffu, sum, o);
    float mean = sum * (1.0f / 256.0f);
    float var = 0.f;
    #pragma unroll
    for (int i = 0; i < 8; i++) { float d = v[i] - mean; var += d * d; }
    #pragma unroll
    for (int o = 16; o > 0; o >>= 1) var += __shfl_xor_sync(0xffffffffu, var, o);
    float inv = rsqrtf(var * (1.0f / 256.0f) + 1e-5f);
    __half* oh = g_hh + (size_t)row * D_;
    __half* ol = g_hl + (size_t)row * D_;
    float asum = 0.f;
    #pragma unroll
    for (int i = 0; i < 8; i++) {
        int c = lane + i * 32;
        float r = (v[i] - mean) * inv * s[c] + bb[c];
        __half h, l; split16(r, h, l);
        oh[c] = h; ol[c] = l;
        asum += r;
    }
    float part = (lane & 1) ? -asum : asum;
    #pragma unroll
    for (int o = 16; o > 0; o >>= 1) part += __shfl_xor_sync(0xffffffffu, part, o);
    if (lane == 0) {
        int b = row / 1025, tok = row - b * 1025;
        g_hc128[b * TP_ + tok] = part;
    }
}

// ---------------- split-fp16 mma DFT, cp.async double-buffer (dyn smem) ------
// MODE 0: Hc = h @ C2      MODE 1: Hs = h @ S2     (M=65600, K=256)
// MODE 2: U  = C1 @ Hc[b]  MODE 3: V  = S1 @ Hs[b] (M=513,   K=1056)
template<int MODE>
__global__ __launch_bounds__(256) void k_dftmma() {
    constexpr bool DIMS = (MODE < 2);
    constexpr int KTOT = DIMS ? 256 : TP_;
    constexpr int NSLAB = KTOT / 32;
    const int MROWS = DIMS ? M_ : TH_;

    extern __shared__ __half dsm[];

    int tid = threadIdx.x;
    int wid = tid >> 5, lane = tid & 31;
    int wm = wid & 3, wn = wid >> 2;
    int m0 = blockIdx.y * 128;
    int b = blockIdx.z;

    const __half *Ah, *Al, *Bh, *Bl;
    if (MODE == 0)      { Ah = g_hh;  Al = g_hl;  Bh = g_C2h; Bl = g_C2l; }
    else if (MODE == 1) { Ah = g_hh;  Al = g_hl;  Bh = g_S2h; Bl = g_S2l; }
    else if (MODE == 2) { Ah = g_C1h; Al = g_C1l;
                          Bh = g_hch + (size_t)b * TP_ * KN_;
                          Bl = g_hcl + (size_t)b * TP_ * KN_; }
    else                { Ah = g_S1h; Al = g_S1l;
                          Bh = g_hsh + (size_t)b * TP_ * KN_;
                          Bl = g_hsl + (size_t)b * TP_ * KN_; }

    float acc[2][8][4] = {};

    // ldsm base addresses (stage 0); stage 1 = +STG_H*2 bytes
    uint32_t ah_addr[2], al_addr[2], bh_addr[4], bl_addr[4];
    #pragma unroll
    for (int mt = 0; mt < 2; mt++) {
        int r = wm * 32 + mt * 16 + (lane & 15);
        int c = (lane >> 4) * 8;
        ah_addr[mt] = (uint32_t)__cvta_generic_to_shared(&dsm[r * 40 + c]);
        al_addr[mt] = (uint32_t)__cvta_generic_to_shared(&dsm[OFF_ASL + r * 40 + c]);
    }
    #pragma unroll
    for (int j = 0; j < 4; j++) {
        int r = lane & 15;
        int c = wn * 64 + j * 16 + (lane >> 4) * 8;
        bh_addr[j] = (uint32_t)__cvta_generic_to_shared(&dsm[OFF_BSH + r * 136 + c]);
        bl_addr[j] = (uint32_t)__cvta_generic_to_shared(&dsm[OFF_BSL + r * 136 + c]);
    }

    // per-thread cp.async geometry: A 2 chunks (hi+lo), B 2 chunks (hi+lo)
    // A: v = tid + l*256 -> row v>>2 (0..127), col (v&3)*8; two l passes
    int a_r[2], a_c[2];
    const __half* a_srch[2];
    const __half* a_srcl[2];
    uint32_t a_dsth[2], a_dstl[2];
    #pragma unroll
    for (int l = 0; l < 2; l++) {
        int v = tid + l * 256;
        a_r[l] = v >> 2; a_c[l] = (v & 3) * 8;
        int am = min(m0 + a_r[l], MROWS - 1);
        a_srch[l] = Ah + (size_t)am * KTOT + a_c[l];
        a_srcl[l] = Al + (size_t)am * KTOT + a_c[l];
        a_dsth[l] = (uint32_t)__cvta_generic_to_shared(&dsm[a_r[l] * 40 + a_c[l]]);
        a_dstl[l] = (uint32_t)__cvta_generic_to_shared(&dsm[OFF_ASL + a_r[l] * 40 + a_c[l]]);
    }
    int b_r[2], b_c[2];
    uint32_t b_dsth[2], b_dstl[2];
    #pragma unroll
    for (int l = 0; l < 2; l++) {
        int v = tid + l * 256;
        b_r[l] = v >> 4; b_c[l] = (v & 15) * 8;
        b_dsth[l] = (uint32_t)__cvta_generic_to_shared(&dsm[OFF_BSH + b_r[l] * 136 + b_c[l]]);
        b_dstl[l] = (uint32_t)__cvta_generic_to_shared(&dsm[OFF_BSL + b_r[l] * 136 + b_c[l]]);
    }

    constexpr uint32_t STG_BYTES = STG_H * 2;   // 37888

    // issue slab 0 into stage 0
    #pragma unroll
    for (int l = 0; l < 2; l++) {
        cpa16(a_dsth[l], a_srch[l]);
        cpa16(a_dstl[l], a_srcl[l]);
        cpa16(b_dsth[l], Bh + (size_t)b_r[l] * KN_ + b_c[l]);
        cpa16(b_dstl[l], Bl + (size_t)b_r[l] * KN_ + b_c[l]);
    }
    cpa_commit();

    for (int ks = 0; ks < NSLAB; ks++) {
        uint32_t so = (uint32_t)(ks & 1) * STG_BYTES;
        if (ks + 1 < NSLAB) {
            int k0 = (ks + 1) * 32;
            uint32_t sn = (uint32_t)((ks + 1) & 1) * STG_BYTES;
            #pragma unroll
            for (int l = 0; l < 2; l++) {
                cpa16(a_dsth[l] + sn, a_srch[l] + k0);
                cpa16(a_dstl[l] + sn, a_srcl[l] + k0);
                cpa16(b_dsth[l] + sn, Bh + (size_t)(k0 + b_r[l]) * KN_ + b_c[l]);
                cpa16(b_dstl[l] + sn, Bl + (size_t)(k0 + b_r[l]) * KN_ + b_c[l]);
            }
            cpa_commit();
            cpa_wait<1>();
        } else {
            cpa_wait<0>();
        }
        __syncthreads();
        #pragma unroll
        for (int ksub = 0; ksub < 2; ksub++) {
            uint32_t afh[2][4], afl[2][4], bfh[4][4], bfl[4][4];
            #pragma unroll
            for (int mt = 0; mt < 2; mt++) {
                ldsm_x4(afh[mt], ah_addr[mt] + so + ksub * 32);
                ldsm_x4(afl[mt], al_addr[mt] + so + ksub * 32);
            }
            #pragma unroll
            for (int j = 0; j < 4; j++) {
                ldsm_x4_t(bfh[j], bh_addr[j] + so + ksub * 4352);
                ldsm_x4_t(bfl[j], bl_addr[j] + so + ksub * 4352);
            }
            #pragma unroll
            for (int mt = 0; mt < 2; mt++)
                #pragma unroll
                for (int nt = 0; nt < 8; nt++) {
                    mma16816(acc[mt][nt], afh[mt], &bfh[nt >> 1][(nt & 1) * 2]);
                    mma16816(acc[mt][nt], afh[mt], &bfl[nt >> 1][(nt & 1) * 2]);
                    mma16816(acc[mt][nt], afl[mt], &bfh[nt >> 1][(nt & 1) * 2]);
                }
        }
        __syncthreads();
    }

    #pragma unroll
    for (int mt = 0; mt < 2; mt++) {
        #pragma unroll
        for (int nt = 0; nt < 8; nt++) {
            int row = m0 + wm * 32 + mt * 16 + (lane >> 2);
            int col = wn * 64 + nt * 8 + (lane & 3) * 2;
            #pragma unroll
            for (int h2 = 0; h2 < 2; h2++) {
                int rr = row + h2 * 8;
                if (DIMS) {
                    if (rr >= M_) continue;
                    int bb = rr / 1025, tok = rr - bb * 1025;
                    size_t off = ((size_t)bb * TP_ + tok) * KN_ + col;
                    #pragma unroll
                    for (int q = 0; q < 2; q++) {
                        __half h, l; split16(acc[mt][nt][h2 * 2 + q], h, l);
                        if (MODE == 0) { g_hch[off + q] = h; g_hcl[off + q] = l; }
                        else           { g_hsh[off + q] = h; g_hsl[off + q] = l; }
                    }
                } else if (MODE == 2) {
                    if (rr >= TH_) continue;
                    size_t off = ((size_t)b * TH_ + rr) * KN_ + col;
                    g_U[off]     = acc[mt][nt][h2 * 2 + 0];
                    g_U[off + 1] = acc[mt][nt][h2 * 2 + 1];
                } else {
                    if (rr >= TH_) continue;
                    const float* urow = g_U + ((size_t)b * TH_ + rr) * KN_;
                    float* tb = g_t + (size_t)b * T_ * D_;
                    #pragma unroll
                    for (int q = 0; q < 2; q++) {
                        int k2 = col + q;
                        float vv = acc[mt][nt][h2 * 2 + q];
                        float u = urow[k2];
                        float upv = u + vv, umv = u - vv;
                        tb[(size_t)rr * D_ + k2] += umv;
                        if (k2 >= 1) tb[(size_t)rr * D_ + (256 - k2)] += upv;
                        if (rr >= 1) {
                            size_t r2 = (size_t)(T_ - rr);
                            tb[r2 * D_ + k2] += upv;
                            if (k2 >= 1) tb[r2 * D_ + (256 - k2)] += umv;
                        }
                    }
                }
            }
        }
    }
}

// ---------------- token-DFT Nyquist column (k2 = 128): V = 0 ----------------
__global__ void k_tok128() {
    int warp = threadIdx.x >> 5, lane = threadIdx.x & 31;
    int k1 = blockIdx.x * 8 + warp;
    int b  = blockIdx.y;
    if (k1 >= TH_) return;
    const float* cr = g_C1f + (size_t)k1 * T_;
    const float* hv = g_hc128 + (size_t)b * TP_;
    float s = 0.f;
    for (int n = lane; n < T_; n += 32) s += cr[n] * hv[n];
    #pragma unroll
    for (int o = 16; o > 0; o >>= 1) s += __shfl_xor_sync(0xffffffffu, s, o);
    if (lane == 0) {
        float* tb = g_t + (size_t)b * T_ * D_;
        tb[(size_t)k1 * D_ + 128] += s;
        if (k1 >= 1) tb[(size_t)(T_ - k1) * D_ + 128] += s;
    }
}

// ---------------- FFN via fp16 tensor cores + cp.async double buffer --------
template<int N, int K, bool FFN1>
__global__ __launch_bounds__(256) void k_ffn_mma(int layer, const float* __restrict__ bias) {
    __shared__ __half As[2][128][40];
    __shared__ __half Bs[2][32][136];
    int tid = threadIdx.x;
    int wid = tid >> 5, lane = tid & 31;
    int wm = wid & 3, wn = wid >> 2;
    int m0 = blockIdx.y * 128, n0 = blockIdx.x * 128;

    const __half* A  = FFN1 ? g_hh : g_mid16;
    const __half* Bw = (FFN1 ? g_w1h : g_w2h) + (size_t)layer * D_ * HID_;

    float acc[2][8][4] = {};

    uint32_t a_addr[2][2], b_addr[2][4];
    #pragma unroll
    for (int bf = 0; bf < 2; bf++) {
        #pragma unroll
        for (int mt = 0; mt < 2; mt++)
            a_addr[bf][mt] = (uint32_t)__cvta_generic_to_shared(
                &As[bf][wm * 32 + mt * 16 + (lane & 15)][(lane >> 4) * 8]);
        #pragma unroll
        for (int j = 0; j < 4; j++)
            b_addr[bf][j] = (uint32_t)__cvta_generic_to_shared(
                &Bs[bf][lane & 15][wn * 64 + j * 16 + (lane >> 4) * 8]);
    }

    int ar = tid >> 1, aco = (tid & 1) * 16;
    int am = min(m0 + ar, M_ - 1);
    const __half* arow = A + (size_t)am * K + aco;
    int br = tid >> 4, bc = (tid & 15) * 8;

    uint32_t a_dst[2];
    uint32_t b_dst[2][2];
    #pragma unroll
    for (int bf = 0; bf < 2; bf++) {
        a_dst[bf] = (uint32_t)__cvta_generic_to_shared(&As[bf][ar][aco]);
        #pragma unroll
        for (int l = 0; l < 2; l++)
            b_dst[bf][l] = (uint32_t)__cvta_generic_to_shared(&Bs[bf][br + l * 16][bc]);
    }

    cpa16(a_dst[0],      arow);
    cpa16(a_dst[0] + 16, arow + 8);
    #pragma unroll
    for (int l = 0; l < 2; l++)
        cpa16(b_dst[0][l], Bw + (size_t)(br + l * 16) * N + n0 + bc);
    cpa_commit();

    constexpr int NSLAB = K / 32;
    for (int ks = 0; ks < NSLAB; ks++) {
        int bf = ks & 1;
        if (ks + 1 < NSLAB) {
            int k0 = (ks + 1) * 32;
            int nb = bf ^ 1;
            cpa16(a_dst[nb],      arow + k0);
            cpa16(a_dst[nb] + 16, arow + k0 + 8);
            #pragma unroll
            for (int l = 0; l < 2; l++)
                cpa16(b_dst[nb][l], Bw + (size_t)(k0 + br + l * 16) * N + n0 + bc);
            cpa_commit();
            cpa_wait<1>();
        } else {
            cpa_wait<0>();
        }
        __syncthreads();
        #pragma unroll
        for (int ksub = 0; ksub < 2; ksub++) {
            uint32_t af[2][4], bfr[4][4];
            #pragma unroll
            for (int mt = 0; mt < 2; mt++) ldsm_x4(af[mt], a_addr[bf][mt] + ksub * 32);
            #pragma unroll
            for (int j = 0; j < 4; j++) ldsm_x4_t(bfr[j], b_addr[bf][j] + ksub * 4352);
            #pragma unroll
            for (int mt = 0; mt < 2; mt++)
                #pragma unroll
                for (int nt = 0; nt < 8; nt++)
                    mma16816(acc[mt][nt], af[mt], &bfr[nt >> 1][(nt & 1) * 2]);
        }
        __syncthreads();
    }

    int r_base = m0 + wm * 32;
    int c_base = n0 + wn * 64;
    #pragma unroll
    for (int mt = 0; mt < 2; mt++) {
        #pragma unroll
        for (int nt = 0; nt < 8; nt++) {
            int row = r_base + mt * 16 + (lane >> 2);
            int col = c_base + nt * 8 + (lane & 3) * 2;
            float bz0 = bias[col], bz1 = bias[col + 1];
            #pragma unroll
            for (int h = 0; h < 2; h++) {
                int rr = row + h * 8;
                if (rr >= M_) continue;
                float v0 = acc[mt][nt][h * 2 + 0] + bz0;
                float v1 = acc[mt][nt][h * 2 + 1] + bz1;
                if (FFN1) {
                    v0 = (v0 > 0.f) ? v0 : 0.01f * v0;
                    v1 = (v1 > 0.f) ? v1 : 0.01f * v1;
                    *(__half2*)&g_mid16[(size_t)rr * N + col] = __floats2half2_rn(v0, v1);
                } else {
                    float2* p = (float2*)&g_t[(size_t)rr * D_ + col];
                    float2 t2 = *p;
                    t2.x += v0; t2.y += v1;
                    *p = t2;
                }
            }
        }
    }
}

// ---------------- mean pool over tokens ----------------
__global__ void k_pool() {
    int b = blockIdx.x, d = threadIdx.x;
    const float* p = g_t + (size_t)b * T_ * D_ + d;
    float s = 0.f;
    for (int tok = 0; tok < T_; tok++) s += p[(size_t)tok * D_];
    g_pool[b * D_ + d] = s * (1.0f / 1025.0f);
}

// ---------------- head: LN + linear + softmax ----------------
__global__ void k_head(const float* __restrict__ s, const float* __restrict__ bb,
                       const float* __restrict__ W, const float* __restrict__ hb,
                       float* __restrict__ out) {
    __shared__ float sh[256];
    __shared__ float lnp[256];
    int b = blockIdx.x, tid = threadIdx.x;
    float x = g_pool[b * D_ + tid];
    sh[tid] = x; __syncthreads();
    for (int o = 128; o > 0; o >>= 1) { if (tid < o) sh[tid] += sh[tid + o]; __syncthreads(); }
    float mean = sh[0] * (1.0f / 256.0f);
    __syncthreads();
    float d = x - mean;
    sh[tid] = d * d; __syncthreads();
    for (int o = 128; o > 0; o >>= 1) { if (tid < o) sh[tid] += sh[tid + o]; __syncthreads(); }
    float inv = rsqrtf(sh[0] * (1.0f / 256.0f) + 1e-5f);
    __syncthreads();
    lnp[tid] = d * inv * s[tid] + bb[tid];
    __syncthreads();
    float lv[4];
    float lmax = -1e30f;
    #pragma unroll
    for (int j = 0; j < 4; j++) {
        int n = tid + j * 256;
        float acc = -1e30f;
        if (n < NC_) {
            acc = hb[n];
            for (int k = 0; k < 256; k++) acc += lnp[k] * W[k * NC_ + n];
            lmax = fmaxf(lmax, acc);
        }
        lv[j] = acc;
    }
    sh[tid] = lmax; __syncthreads();
    for (int o = 128; o > 0; o >>= 1) { if (tid < o) sh[tid] = fmaxf(sh[tid], sh[tid + o]); __syncthreads(); }
    float mx = sh[0]; __syncthreads();
    float esum = 0.f;
    #pragma unroll
    for (int j = 0; j < 4; j++) {
        int n = tid + j * 256;
        if (n < NC_) esum += expf(lv[j] - mx);
    }
    sh[tid] = esum; __syncthreads();
    for (int o = 128; o > 0; o >>= 1) { if (tid < o) sh[tid] += sh[tid + o]; __syncthreads(); }
    float tot = sh[0];
    #pragma unroll
    for (int j = 0; j < 4; j++) {
        int n = tid + j * 256;
        if (n < NC_) out[b * NC_ + n] = expf(lv[j] - mx) / tot;
    }
}

// ---------------- launch ----------------
extern "C" void kernel_launch(void* const* d_in, const int* in_sizes, int n_in,
                              void* d_out, int out_size) {
    const float* x      = (const float*)d_in[0];
    const float* conv_w = (const float*)d_in[1];
    const float* conv_b = (const float*)d_in[2];
    const float* pos    = (const float*)d_in[3];
    const float* cls    = (const float*)d_in[4];
    const float* ln1_s  = (const float*)d_in[5];
    const float* ln1_b  = (const float*)d_in[6];
    const float* ln2_s  = (const float*)d_in[7];
    const float* ln2_b  = (const float*)d_in[8];
    const float* w1     = (const float*)d_in[9];
    const float* b1     = (const float*)d_in[10];
    const float* w2     = (const float*)d_in[11];
    const float* b2     = (const float*)d_in[12];
    const float* hls    = (const float*)d_in[13];
    const float* hlb    = (const float*)d_in[14];
    const float* hw     = (const float*)d_in[15];
    const float* hb     = (const float*)d_in[16];
    float* out = (float*)d_out;

    // allow 75.8 KB dynamic smem on the DFT kernels (attribute set is
    // idempotent, not a stream op; safe under graph capture)
    cudaFuncSetAttribute(k_dftmma<0>, cudaFuncAttributeMaxDynamicSharedMemorySize, SMEM_DFT_BYTES);
    cudaFuncSetAttribute(k_dftmma<1>, cudaFuncAttributeMaxDynamicSharedMemorySize, SMEM_DFT_BYTES);
    cudaFuncSetAttribute(k_dftmma<2>, cudaFuncAttributeMaxDynamicSharedMemorySize, SMEM_DFT_BYTES);
    cudaFuncSetAttribute(k_dftmma<3>, cudaFuncAttributeMaxDynamicSharedMemorySize, SMEM_DFT_BYTES);

    k_init1f<<<(TH_ * T_ + 255) / 256, 256>>>();
    k_init1s<<<(TH_ * TP_ + 255) / 256, 256>>>();
    k_init2s<<<(D_ * KN_ + 255) / 256, 256>>>();
    k_twt<<<(KC_ * D_ + 255) / 256, 256>>>(conv_w);
    k_cvtw<<<(L_ * D_ * HID_ + 255) / 256, 256>>>(w1, w2);
    k_patch<<<dim3(D_ / 64, (B_ * NP_) / 64), 256>>>(x, conv_b, pos);
    k_cls<<<(B_ * D_) / 256, 256>>>(cls, pos);

    const int MB  = (M_ + 127) / 128;    // 513
    const int MBT = (TH_ + 127) / 128;   // 5
    for (int i = 0; i < L_; i++) {
        k_ln<<<(B_ * T_) / 8, 256>>>(ln1_s + i * D_, ln1_b + i * D_);
        k_dftmma<0><<<dim3(1, MB, 1), 256, SMEM_DFT_BYTES>>>();
        k_dftmma<1><<<dim3(1, MB, 1), 256, SMEM_DFT_BYTES>>>();
        k_dftmma<2><<<dim3(1, MBT, B_), 256, SMEM_DFT_BYTES>>>();
        k_dftmma<3><<<dim3(1, MBT, B_), 256, SMEM_DFT_BYTES>>>();
        k_tok128<<<dim3((TH_ + 7) / 8, B_), 256>>>();
        k_ln<<<(B_ * T_) / 8, 256>>>(ln2_s + i * D_, ln2_b + i * D_);
        k_ffn_mma<HID_, D_, true ><<<dim3(HID_ / 128, MB), 256>>>(i, b1 + i * HID_);
        k_ffn_mma<D_, HID_, false><<<dim3(D_ / 128, MB), 256>>>(i, b2 + i * D_);
    }

    k_pool<<<B_, D_>>>();
    k_head<<<B_, 256>>>(hls, hlb, hw, hb, out);
}

// round 15
// speedup vs baseline: 1.2011x; 1.2011x over previous
#include <cuda_runtime.h>
#include <cuda_fp16.h>
#include <stdint.h>
#include <math.h>

// ---------------- problem constants ----------------
constexpr int B_   = 64;
constexpr int C_   = 3;
constexpr int HW_  = 512;
constexpr int P_   = 16;
constexpr int D_   = 256;    // token dim
constexpr int G_   = 32;     // GH = GW
constexpr int NP_  = 1024;
constexpr int T_   = 1025;   // tokens (NP+1)
constexpr int TH_  = 513;    // half-spectrum rows (0..512)
constexpr int TP_  = 1056;   // tokens padded to 32-multiple for mma K loop
constexpr int HID_ = 1024;
constexpr int L_   = 6;
constexpr int NC_  = 1000;
constexpr int KH_  = 129;    // half-spectrum columns (0..128)
constexpr int KN_  = 128;    // mma-handled spectrum columns (0..127)
constexpr int KC_  = 768;    // C*P*P
constexpr int M_   = B_ * T_;   // 65600 rows
constexpr int MP_  = B_ * NP_;  // 65536 patch rows

// ---------------- scratch (device globals; no allocation) ----------------
__device__ float  g_t   [B_*T_*D_];        // residual stream
__device__ __half g_hh  [B_*T_*D_];        // LN output, fp16 hi
__device__ __half g_hl  [B_*T_*D_];        // LN output, fp16 lo
__device__ float  g_hc128[B_*TP_];         // dim-DFT Nyquist col (alternating sums)
__device__ __half g_hch [B_*TP_*KN_];      // Hc hi (pad token rows zero)
__device__ __half g_hcl [B_*TP_*KN_];      // Hc lo
__device__ __half g_hsh [B_*TP_*KN_];      // Hs hi
__device__ __half g_hsl [B_*TP_*KN_];      // Hs lo
__device__ float  g_U   [B_*TH_*KN_];      // token-DFT cosine part
__device__ __half g_mid16[B_*T_*HID_];
__device__ float  g_C1f [TH_*T_];          // fp32 C1 rows 0..512 (Nyquist MV)
__device__ __half g_C1h [TH_*TP_];         // split token-DFT matrices (pad cols zero)
__device__ __half g_C1l [TH_*TP_];
__device__ __half g_S1h [TH_*TP_];
__device__ __half g_S1l [TH_*TP_];
__device__ __half g_C2h [D_*KN_];          // split dim-DFT matrices
__device__ __half g_C2l [D_*KN_];
__device__ __half g_S2h [D_*KN_];
__device__ __half g_S2l [D_*KN_];
__device__ __half g_wTh [KC_*D_];          // split transposed conv weight
__device__ __half g_wTl [KC_*D_];
__device__ float  g_pool[B_*D_];
__device__ __half g_w1h [L_*D_*HID_];
__device__ __half g_w2h [L_*HID_*D_];

// ---------------- mma / cp.async helpers (spaces after braces: template-
// renderer safe) ----------------
__device__ __forceinline__ void ldsm_x4(uint32_t* r, uint32_t addr) {
    asm volatile("ldmatrix.sync.aligned.m8n8.x4.shared.b16 { %0, %1, %2, %3 }, [ %4 ];"
                 : "=r"(r[0]), "=r"(r[1]), "=r"(r[2]), "=r"(r[3]) : "r"(addr));
}
__device__ __forceinline__ void ldsm_x4_t(uint32_t* r, uint32_t addr) {
    asm volatile("ldmatrix.sync.aligned.m8n8.x4.trans.shared.b16 { %0, %1, %2, %3 }, [ %4 ];"
                 : "=r"(r[0]), "=r"(r[1]), "=r"(r[2]), "=r"(r[3]) : "r"(addr));
}
__device__ __forceinline__ void mma16816(float* d, const uint32_t* a, const uint32_t* b) {
    asm volatile("mma.sync.aligned.m16n8k16.row.col.f32.f16.f16.f32 "
                 "{ %0, %1, %2, %3 }, { %4, %5, %6, %7 }, { %8, %9 }, { %0, %1, %2, %3 };"
                 : "+f"(d[0]), "+f"(d[1]), "+f"(d[2]), "+f"(d[3])
                 : "r"(a[0]), "r"(a[1]), "r"(a[2]), "r"(a[3]), "r"(b[0]), "r"(b[1]));
}
__device__ __forceinline__ void split16(float x, __half& h, __half& l) {
    h = __float2half(x);
    l = __float2half(x - __half2float(h));
}
__device__ __forceinline__ void cpa16(uint32_t dst, const void* src) {
    asm volatile("cp.async.cg.shared.global [ %0 ], [ %1 ], 16;" :: "r"(dst), "l"(src));
}
__device__ __forceinline__ void cpa_commit() {
    asm volatile("cp.async.commit_group;");
}
template<int W>
__device__ __forceinline__ void cpa_wait() {
    asm volatile("cp.async.wait_group %0;" :: "n"(W));
}

// ---------------- init kernels ----------------
__global__ void k_init1f() {       // fp32 C1, rows 0..512
    int idx = blockIdx.x * blockDim.x + threadIdx.x;
    if (idx >= TH_ * T_) return;
    int k = idx / T_, n = idx % T_;
    int prod = (int)(((long long)k * n) % T_);
    g_C1f[idx] = cosf((float)(6.283185307179586 * (double)prod / (double)T_));
}

__global__ void k_init1s() {       // split fp16 C1/S1, rows 0..512, cols padded
    int idx = blockIdx.x * blockDim.x + threadIdx.x;
    if (idx >= TH_ * TP_) return;
    int k = idx / TP_, n = idx % TP_;
    float c = 0.f, s = 0.f;
    if (n < T_) {
        int prod = (int)(((long long)k * n) % T_);
        float ang = (float)(6.283185307179586 * (double)prod / (double)T_);
        sincosf(ang, &s, &c);
    }
    __half h, l;
    split16(c, h, l); g_C1h[idx] = h; g_C1l[idx] = l;
    split16(s, h, l); g_S1h[idx] = h; g_S1l[idx] = l;
}

__global__ void k_init2s() {       // split fp16 C2/S2, cols 0..127
    int idx = blockIdx.x * blockDim.x + threadIdx.x;
    if (idx >= D_ * KN_) return;
    int n2 = idx / KN_, k2 = idx % KN_;
    int prod = (n2 * k2) & (D_ - 1);
    float ang = (float)(6.283185307179586 * (double)prod / (double)D_);
    float s, c; sincosf(ang, &s, &c);
    __half h, l;
    split16(c, h, l); g_C2h[idx] = h; g_C2l[idx] = l;
    split16(s, h, l); g_S2h[idx] = h; g_S2l[idx] = l;
}

__global__ void k_twts(const float* __restrict__ w) {   // split transposed conv w
    int idx = blockIdx.x * blockDim.x + threadIdx.x;
    if (idx >= KC_ * D_) return;
    int k = idx >> 8, d = idx & 255;
    __half h, l; split16(w[d * KC_ + k], h, l);
    g_wTh[idx] = h; g_wTl[idx] = l;
}

__global__ void k_cvtw(const float* __restrict__ w1, const float* __restrict__ w2) {
    int i = blockIdx.x * blockDim.x + threadIdx.x;
    if (i >= L_ * D_ * HID_) return;
    g_w1h[i] = __float2half(w1[i]);
    g_w2h[i] = __float2half(w2[i]);
}

__global__ void k_cls(const float* __restrict__ cls, const float* __restrict__ pos) {
    int idx = blockIdx.x * blockDim.x + threadIdx.x;
    int b = idx >> 8, d = idx & 255;
    g_t[(size_t)b * T_ * D_ + d] = cls[d] + pos[d];
}

// ---------------- patch-embed via split-fp16 mma (serial slabs) --------------
// t[b, 1+patch, n] = sum_k x_gather[r, k] * wT[k, n] + cb[n] + pos[1+patch, n]
// M = 65536, N = 256 (two 128-col tiles), K = 768 (24 slabs of 32).
__global__ __launch_bounds__(256) void k_patch_mma(
        const float* __restrict__ x, const float* __restrict__ cb,
        const float* __restrict__ pos) {
    __shared__ __half Ash[128][40];
    __shared__ __half Asl[128][40];
    __shared__ __half Bsh[32][136];
    __shared__ __half Bsl[32][136];

    int tid = threadIdx.x;
    int wid = tid >> 5, lane = tid & 31;
    int wm = wid & 3, wn = wid >> 2;
    int m0 = blockIdx.y * 128, n0 = blockIdx.x * 128;

    // A gather: 2 threads per row, 16 contiguous k each (16-aligned chunks)
    int ar = tid >> 1, ac = (tid & 1) * 16;
    int rrow = m0 + ar;
    int pb_ = rrow >> 10, patch = rrow & 1023;
    int gh = patch >> 5, gw = patch & 31;

    int br = tid >> 4, bc = (tid & 15) * 8;

    float acc[2][8][4] = {};

    uint32_t ah_addr[2], al_addr[2], bh_addr[4], bl_addr[4];
    #pragma unroll
    for (int mt = 0; mt < 2; mt++) {
        ah_addr[mt] = (uint32_t)__cvta_generic_to_shared(
            &Ash[wm * 32 + mt * 16 + (lane & 15)][(lane >> 4) * 8]);
        al_addr[mt] = (uint32_t)__cvta_generic_to_shared(
            &Asl[wm * 32 + mt * 16 + (lane & 15)][(lane >> 4) * 8]);
    }
    #pragma unroll
    for (int j = 0; j < 4; j++) {
        bh_addr[j] = (uint32_t)__cvta_generic_to_shared(
            &Bsh[lane & 15][wn * 64 + j * 16 + (lane >> 4) * 8]);
        bl_addr[j] = (uint32_t)__cvta_generic_to_shared(
            &Bsl[lane & 15][wn * 64 + j * 16 + (lane >> 4) * 8]);
    }

    for (int k0 = 0; k0 < KC_; k0 += 32) {
        // A: load 16 floats, split to hi/lo, store as 2+2 uint4
        {
            int kg = k0 + ac;
            int c = kg >> 8, p = (kg >> 4) & 15;
            const float* src = x + (((size_t)(pb_ * 3 + c) * 512) + gh * 16 + p) * 512 + gw * 16;
            __half hh[16], ll[16];
            #pragma unroll
            for (int v4 = 0; v4 < 4; v4++) {
                float4 f = *(const float4*)(src + v4 * 4);
                split16(f.x, hh[v4 * 4 + 0], ll[v4 * 4 + 0]);
                split16(f.y, hh[v4 * 4 + 1], ll[v4 * 4 + 1]);
                split16(f.z, hh[v4 * 4 + 2], ll[v4 * 4 + 2]);
                split16(f.w, hh[v4 * 4 + 3], ll[v4 * 4 + 3]);
            }
            *(uint4*)&Ash[ar][ac]     = *(const uint4*)&hh[0];
            *(uint4*)&Ash[ar][ac + 8] = *(const uint4*)&hh[8];
            *(uint4*)&Asl[ar][ac]     = *(const uint4*)&ll[0];
            *(uint4*)&Asl[ar][ac + 8] = *(const uint4*)&ll[8];
        }
        // B: pre-split weights, straight uint4 copies
        #pragma unroll
        for (int l = 0; l < 2; l++) {
            int rbr = k0 + br + l * 16;
            *(uint4*)&Bsh[br + l * 16][bc] = *(const uint4*)(g_wTh + (size_t)rbr * D_ + n0 + bc);
            *(uint4*)&Bsl[br + l * 16][bc] = *(const uint4*)(g_wTl + (size_t)rbr * D_ + n0 + bc);
        }
        __syncthreads();
        #pragma unroll
        for (int ksub = 0; ksub < 2; ksub++) {
            uint32_t afh[2][4], afl[2][4], bfh[4][4], bfl[4][4];
            #pragma unroll
            for (int mt = 0; mt < 2; mt++) {
                ldsm_x4(afh[mt], ah_addr[mt] + ksub * 32);
                ldsm_x4(afl[mt], al_addr[mt] + ksub * 32);
            }
            #pragma unroll
            for (int j = 0; j < 4; j++) {
                ldsm_x4_t(bfh[j], bh_addr[j] + ksub * 4352);
                ldsm_x4_t(bfl[j], bl_addr[j] + ksub * 4352);
            }
            #pragma unroll
            for (int mt = 0; mt < 2; mt++)
                #pragma unroll
                for (int nt = 0; nt < 8; nt++) {
                    mma16816(acc[mt][nt], afh[mt], &bfh[nt >> 1][(nt & 1) * 2]);
                    mma16816(acc[mt][nt], afh[mt], &bfl[nt >> 1][(nt & 1) * 2]);
                    mma16816(acc[mt][nt], afl[mt], &bfh[nt >> 1][(nt & 1) * 2]);
                }
        }
        __syncthreads();
    }

    #pragma unroll
    for (int mt = 0; mt < 2; mt++) {
        #pragma unroll
        for (int nt = 0; nt < 8; nt++) {
            int row = m0 + wm * 32 + mt * 16 + (lane >> 2);
            int col = n0 + wn * 64 + nt * 8 + (lane & 3) * 2;
            #pragma unroll
            for (int h2 = 0; h2 < 2; h2++) {
                int rr = row + h2 * 8;
                int b = rr >> 10, pt = rr & 1023;
                size_t base = ((size_t)b * T_ + 1 + pt) * D_;
                #pragma unroll
                for (int q = 0; q < 2; q++) {
                    g_t[base + col + q] = acc[mt][nt][h2 * 2 + q]
                        + cb[col + q] + pos[(1 + pt) * D_ + col + q];
                }
            }
        }
    }
}

// ---------------- LayerNorm -> split fp16 (hi, lo) + Nyquist alt-sum --------
__global__ void k_ln(const float* __restrict__ s, const float* __restrict__ bb) {
    int row  = blockIdx.x * 8 + (threadIdx.x >> 5);
    int lane = threadIdx.x & 31;
    const float* x = g_t + (size_t)row * D_;
    float v[8]; float sum = 0.f;
    #pragma unroll
    for (int i = 0; i < 8; i++) { v[i] = x[lane + i * 32]; sum += v[i]; }
    #pragma unroll
    for (int o = 16; o > 0; o >>= 1) sum += __shfl_xor_sync(0xffffffffu, sum, o);
    float mean = sum * (1.0f / 256.0f);
    float var = 0.f;
    #pragma unroll
    for (int i = 0; i < 8; i++) { float d = v[i] - mean; var += d * d; }
    #pragma unroll
    for (int o = 16; o > 0; o >>= 1) var += __shfl_xor_sync(0xffffffffu, var, o);
    float inv = rsqrtf(var * (1.0f / 256.0f) + 1e-5f);
    __half* oh = g_hh + (size_t)row * D_;
    __half* ol = g_hl + (size_t)row * D_;
    float asum = 0.f;
    #pragma unroll
    for (int i = 0; i < 8; i++) {
        int c = lane + i * 32;
        float r = (v[i] - mean) * inv * s[c] + bb[c];
        __half h, l; split16(r, h, l);
        oh[c] = h; ol[c] = l;
        asum += r;
    }
    float part = (lane & 1) ? -asum : asum;
    #pragma unroll
    for (int o = 16; o > 0; o >>= 1) part += __shfl_xor_sync(0xffffffffu, part, o);
    if (lane == 0) {
        int b = row / 1025, tok = row - b * 1025;
        g_hc128[b * TP_ + tok] = part;
    }
}

// ---------------- split-fp16 mma GEMM for both DFT stages (R9/R11 form) ------
// MODE 0: Hc = h @ C2      MODE 1: Hs = h @ S2     (M=65600, K=256)
// MODE 2: U  = C1 @ Hc[b]  MODE 3: V  = S1 @ Hs[b] (M=513,   K=1056)
template<int MODE>
__global__ void k_dftmma() {
    constexpr bool DIMS = (MODE < 2);
    constexpr int KTOT = DIMS ? 256 : TP_;
    constexpr int NSLAB = KTOT / 32;
    const int MROWS = DIMS ? M_ : TH_;

    __shared__ __half Ash[128][40];
    __shared__ __half Asl[128][40];
    __shared__ __half Bsh[32][136];
    __shared__ __half Bsl[32][136];

    int tid = threadIdx.x;
    int wid = tid >> 5, lane = tid & 31;
    int wm = wid & 3, wn = wid >> 2;
    int m0 = blockIdx.y * 128;
    int b = blockIdx.z;

    const __half *Ah, *Al, *Bh, *Bl;
    if (MODE == 0)      { Ah = g_hh;  Al = g_hl;  Bh = g_C2h; Bl = g_C2l; }
    else if (MODE == 1) { Ah = g_hh;  Al = g_hl;  Bh = g_S2h; Bl = g_S2l; }
    else if (MODE == 2) { Ah = g_C1h; Al = g_C1l;
                          Bh = g_hch + (size_t)b * TP_ * KN_;
                          Bl = g_hcl + (size_t)b * TP_ * KN_; }
    else                { Ah = g_S1h; Al = g_S1l;
                          Bh = g_hsh + (size_t)b * TP_ * KN_;
                          Bl = g_hsl + (size_t)b * TP_ * KN_; }

    float acc[2][8][4] = {};

    uint32_t ah_addr[2], al_addr[2], bh_addr[4], bl_addr[4];
    #pragma unroll
    for (int mt = 0; mt < 2; mt++) {
        ah_addr[mt] = (uint32_t)__cvta_generic_to_shared(
            &Ash[wm * 32 + mt * 16 + (lane & 15)][(lane >> 4) * 8]);
        al_addr[mt] = (uint32_t)__cvta_generic_to_shared(
            &Asl[wm * 32 + mt * 16 + (lane & 15)][(lane >> 4) * 8]);
    }
    #pragma unroll
    for (int j = 0; j < 4; j++) {
        bh_addr[j] = (uint32_t)__cvta_generic_to_shared(
            &Bsh[lane & 15][wn * 64 + j * 16 + (lane >> 4) * 8]);
        bl_addr[j] = (uint32_t)__cvta_generic_to_shared(
            &Bsl[lane & 15][wn * 64 + j * 16 + (lane >> 4) * 8]);
    }

    for (int ks = 0; ks < NSLAB; ks++) {
        int k0 = ks * 32;
        #pragma unroll
        for (int l = 0; l < 2; l++) {
            int v = tid + l * 256;
            int ar = v >> 2, ac = (v & 3) * 8;
            int am = min(m0 + ar, MROWS - 1);
            *(uint4*)&Ash[ar][ac] = *(const uint4*)(Ah + (size_t)am * KTOT + k0 + ac);
            *(uint4*)&Asl[ar][ac] = *(const uint4*)(Al + (size_t)am * KTOT + k0 + ac);
        }
        #pragma unroll
        for (int l = 0; l < 2; l++) {
            int v = tid + l * 256;
            int br = v >> 4, bc = (v & 15) * 8;
            *(uint4*)&Bsh[br][bc] = *(const uint4*)(Bh + (size_t)(k0 + br) * KN_ + bc);
            *(uint4*)&Bsl[br][bc] = *(const uint4*)(Bl + (size_t)(k0 + br) * KN_ + bc);
        }
        __syncthreads();
        #pragma unroll
        for (int ksub = 0; ksub < 2; ksub++) {
            uint32_t afh[2][4], afl[2][4], bfh[4][4], bfl[4][4];
            #pragma unroll
            for (int mt = 0; mt < 2; mt++) {
                ldsm_x4(afh[mt], ah_addr[mt] + ksub * 32);
                ldsm_x4(afl[mt], al_addr[mt] + ksub * 32);
            }
            #pragma unroll
            for (int j = 0; j < 4; j++) {
                ldsm_x4_t(bfh[j], bh_addr[j] + ksub * 4352);
                ldsm_x4_t(bfl[j], bl_addr[j] + ksub * 4352);
            }
            #pragma unroll
            for (int mt = 0; mt < 2; mt++)
                #pragma unroll
                for (int nt = 0; nt < 8; nt++) {
                    mma16816(acc[mt][nt], afh[mt], &bfh[nt >> 1][(nt & 1) * 2]);
                    mma16816(acc[mt][nt], afh[mt], &bfl[nt >> 1][(nt & 1) * 2]);
                    mma16816(acc[mt][nt], afl[mt], &bfh[nt >> 1][(nt & 1) * 2]);
                }
        }
        __syncthreads();
    }

    #pragma unroll
    for (int mt = 0; mt < 2; mt++) {
        #pragma unroll
        for (int nt = 0; nt < 8; nt++) {
            int row = m0 + wm * 32 + mt * 16 + (lane >> 2);
            int col = wn * 64 + nt * 8 + (lane & 3) * 2;
            #pragma unroll
            for (int h2 = 0; h2 < 2; h2++) {
                int rr = row + h2 * 8;
                if (DIMS) {
                    if (rr >= M_) continue;
                    int bb = rr / 1025, tok = rr - bb * 1025;
                    size_t off = ((size_t)bb * TP_ + tok) * KN_ + col;
                    #pragma unroll
                    for (int q = 0; q < 2; q++) {
                        __half h, l; split16(acc[mt][nt][h2 * 2 + q], h, l);
                        if (MODE == 0) { g_hch[off + q] = h; g_hcl[off + q] = l; }
                        else           { g_hsh[off + q] = h; g_hsl[off + q] = l; }
                    }
                } else if (MODE == 2) {
                    if (rr >= TH_) continue;
                    size_t off = ((size_t)b * TH_ + rr) * KN_ + col;
                    g_U[off]     = acc[mt][nt][h2 * 2 + 0];
                    g_U[off + 1] = acc[mt][nt][h2 * 2 + 1];
                } else {
                    if (rr >= TH_) continue;
                    const float* urow = g_U + ((size_t)b * TH_ + rr) * KN_;
                    float* tb = g_t + (size_t)b * T_ * D_;
                    #pragma unroll
                    for (int q = 0; q < 2; q++) {
                        int k2 = col + q;
                        float vv = acc[mt][nt][h2 * 2 + q];
                        float u = urow[k2];
                        float upv = u + vv, umv = u - vv;
                        tb[(size_t)rr * D_ + k2] += umv;
                        if (k2 >= 1) tb[(size_t)rr * D_ + (256 - k2)] += upv;
                        if (rr >= 1) {
                            size_t r2 = (size_t)(T_ - rr);
                            tb[r2 * D_ + k2] += upv;
                            if (k2 >= 1) tb[r2 * D_ + (256 - k2)] += umv;
                        }
                    }
                }
            }
        }
    }
}

// ---------------- token-DFT Nyquist column (k2 = 128): V = 0 ----------------
__global__ void k_tok128() {
    int warp = threadIdx.x >> 5, lane = threadIdx.x & 31;
    int k1 = blockIdx.x * 8 + warp;
    int b  = blockIdx.y;
    if (k1 >= TH_) return;
    const float* cr = g_C1f + (size_t)k1 * T_;
    const float* hv = g_hc128 + (size_t)b * TP_;
    float s = 0.f;
    for (int n = lane; n < T_; n += 32) s += cr[n] * hv[n];
    #pragma unroll
    for (int o = 16; o > 0; o >>= 1) s += __shfl_xor_sync(0xffffffffu, s, o);
    if (lane == 0) {
        float* tb = g_t + (size_t)b * T_ * D_;
        tb[(size_t)k1 * D_ + 128] += s;
        if (k1 >= 1) tb[(size_t)(T_ - k1) * D_ + 128] += s;
    }
}

// ---------------- FFN via fp16 tensor cores + cp.async double buffer --------
template<int N, int K, bool FFN1>
__global__ __launch_bounds__(256) void k_ffn_mma(int layer, const float* __restrict__ bias) {
    __shared__ __half As[2][128][40];
    __shared__ __half Bs[2][32][136];
    int tid = threadIdx.x;
    int wid = tid >> 5, lane = tid & 31;
    int wm = wid & 3, wn = wid >> 2;
    int m0 = blockIdx.y * 128, n0 = blockIdx.x * 128;

    const __half* A  = FFN1 ? g_hh : g_mid16;
    const __half* Bw = (FFN1 ? g_w1h : g_w2h) + (size_t)layer * D_ * HID_;

    float acc[2][8][4] = {};

    uint32_t a_addr[2][2], b_addr[2][4];
    #pragma unroll
    for (int bf = 0; bf < 2; bf++) {
        #pragma unroll
        for (int mt = 0; mt < 2; mt++)
            a_addr[bf][mt] = (uint32_t)__cvta_generic_to_shared(
                &As[bf][wm * 32 + mt * 16 + (lane & 15)][(lane >> 4) * 8]);
        #pragma unroll
        for (int j = 0; j < 4; j++)
            b_addr[bf][j] = (uint32_t)__cvta_generic_to_shared(
                &Bs[bf][lane & 15][wn * 64 + j * 16 + (lane >> 4) * 8]);
    }

    int ar = tid >> 1, aco = (tid & 1) * 16;
    int am = min(m0 + ar, M_ - 1);
    const __half* arow = A + (size_t)am * K + aco;
    int br = tid >> 4, bc = (tid & 15) * 8;

    uint32_t a_dst[2];
    uint32_t b_dst[2][2];
    #pragma unroll
    for (int bf = 0; bf < 2; bf++) {
        a_dst[bf] = (uint32_t)__cvta_generic_to_shared(&As[bf][ar][aco]);
        #pragma unroll
        for (int l = 0; l < 2; l++)
            b_dst[bf][l] = (uint32_t)__cvta_generic_to_shared(&Bs[bf][br + l * 16][bc]);
    }

    cpa16(a_dst[0],      arow);
    cpa16(a_dst[0] + 16, arow + 8);
    #pragma unroll
    for (int l = 0; l < 2; l++)
        cpa16(b_dst[0][l], Bw + (size_t)(br + l * 16) * N + n0 + bc);
    cpa_commit();

    constexpr int NSLAB = K / 32;
    for (int ks = 0; ks < NSLAB; ks++) {
        int bf = ks & 1;
        if (ks + 1 < NSLAB) {
            int k0 = (ks + 1) * 32;
            int nb = bf ^ 1;
            cpa16(a_dst[nb],      arow + k0);
            cpa16(a_dst[nb] + 16, arow + k0 + 8);
            #pragma unroll
            for (int l = 0; l < 2; l++)
                cpa16(b_dst[nb][l], Bw + (size_t)(k0 + br + l * 16) * N + n0 + bc);
            cpa_commit();
            cpa_wait<1>();
        } else {
            cpa_wait<0>();
        }
        __syncthreads();
        #pragma unroll
        for (int ksub = 0; ksub < 2; ksub++) {
            uint32_t af[2][4], bfr[4][4];
            #pragma unroll
            for (int mt = 0; mt < 2; mt++) ldsm_x4(af[mt], a_addr[bf][mt] + ksub * 32);
            #pragma unroll
            for (int j = 0; j < 4; j++) ldsm_x4_t(bfr[j], b_addr[bf][j] + ksub * 4352);
            #pragma unroll
            for (int mt = 0; mt < 2; mt++)
                #pragma unroll
                for (int nt = 0; nt < 8; nt++)
                    mma16816(acc[mt][nt], af[mt], &bfr[nt >> 1][(nt & 1) * 2]);
        }
        __syncthreads();
    }

    int r_base = m0 + wm * 32;
    int c_base = n0 + wn * 64;
    #pragma unroll
    for (int mt = 0; mt < 2; mt++) {
        #pragma unroll
        for (int nt = 0; nt < 8; nt++) {
            int row = r_base + mt * 16 + (lane >> 2);
            int col = c_base + nt * 8 + (lane & 3) * 2;
            float bz0 = bias[col], bz1 = bias[col + 1];
            #pragma unroll
            for (int h = 0; h < 2; h++) {
                int rr = row + h * 8;
                if (rr >= M_) continue;
                float v0 = acc[mt][nt][h * 2 + 0] + bz0;
                float v1 = acc[mt][nt][h * 2 + 1] + bz1;
                if (FFN1) {
                    v0 = (v0 > 0.f) ? v0 : 0.01f * v0;
                    v1 = (v1 > 0.f) ? v1 : 0.01f * v1;
                    *(__half2*)&g_mid16[(size_t)rr * N + col] = __floats2half2_rn(v0, v1);
                } else {
                    float2* p = (float2*)&g_t[(size_t)rr * D_ + col];
                    float2 t2 = *p;
                    t2.x += v0; t2.y += v1;
                    *p = t2;
                }
            }
        }
    }
}

// ---------------- mean pool over tokens ----------------
__global__ void k_pool() {
    int b = blockIdx.x, d = threadIdx.x;
    const float* p = g_t + (size_t)b * T_ * D_ + d;
    float s = 0.f;
    for (int tok = 0; tok < T_; tok++) s += p[(size_t)tok * D_];
    g_pool[b * D_ + d] = s * (1.0f / 1025.0f);
}

// ---------------- head: LN + linear + softmax ----------------
__global__ void k_head(const float* __restrict__ s, const float* __restrict__ bb,
                       const float* __restrict__ W, const float* __restrict__ hb,
                       float* __restrict__ out) {
    __shared__ float sh[256];
    __shared__ float lnp[256];
    int b = blockIdx.x, tid = threadIdx.x;
    float x = g_pool[b * D_ + tid];
    sh[tid] = x; __syncthreads();
    for (int o = 128; o > 0; o >>= 1) { if (tid < o) sh[tid] += sh[tid + o]; __syncthreads(); }
    float mean = sh[0] * (1.0f / 256.0f);
    __syncthreads();
    float d = x - mean;
    sh[tid] = d * d; __syncthreads();
    for (int o = 128; o > 0; o >>= 1) { if (tid < o) sh[tid] += sh[tid + o]; __syncthreads(); }
    float inv = rsqrtf(sh[0] * (1.0f / 256.0f) + 1e-5f);
    __syncthreads();
    lnp[tid] = d * inv * s[tid] + bb[tid];
    __syncthreads();
    float lv[4];
    float lmax = -1e30f;
    #pragma unroll
    for (int j = 0; j < 4; j++) {
        int n = tid + j * 256;
        float acc = -1e30f;
        if (n < NC_) {
            acc = hb[n];
            for (int k = 0; k < 256; k++) acc += lnp[k] * W[k * NC_ + n];
            lmax = fmaxf(lmax, acc);
        }
        lv[j] = acc;
    }
    sh[tid] = lmax; __syncthreads();
    for (int o = 128; o > 0; o >>= 1) { if (tid < o) sh[tid] = fmaxf(sh[tid], sh[tid + o]); __syncthreads(); }
    float mx = sh[0]; __syncthreads();
    float esum = 0.f;
    #pragma unroll
    for (int j = 0; j < 4; j++) {
        int n = tid + j * 256;
        if (n < NC_) esum += expf(lv[j] - mx);
    }
    sh[tid] = esum; __syncthreads();
    for (int o = 128; o > 0; o >>= 1) { if (tid < o) sh[tid] += sh[tid + o]; __syncthreads(); }
    float tot = sh[0];
    #pragma unroll
    for (int j = 0; j < 4; j++) {
        int n = tid + j * 256;
        if (n < NC_) out[b * NC_ + n] = expf(lv[j] - mx) / tot;
    }
}

// ---------------- launch ----------------
extern "C" void kernel_launch(void* const* d_in, const int* in_sizes, int n_in,
                              void* d_out, int out_size) {
    const float* x      = (const float*)d_in[0];
    const float* conv_w = (const float*)d_in[1];
    const float* conv_b = (const float*)d_in[2];
    const float* pos    = (const float*)d_in[3];
    const float* cls    = (const float*)d_in[4];
    const float* ln1_s  = (const float*)d_in[5];
    const float* ln1_b  = (const float*)d_in[6];
    const float* ln2_s  = (const float*)d_in[7];
    const float* ln2_b  = (const float*)d_in[8];
    const float* w1     = (const float*)d_in[9];
    const float* b1     = (const float*)d_in[10];
    const float* w2     = (const float*)d_in[11];
    const float* b2     = (const float*)d_in[12];
    const float* hls    = (const float*)d_in[13];
    const float* hlb    = (const float*)d_in[14];
    const float* hw     = (const float*)d_in[15];
    const float* hb     = (const float*)d_in[16];
    float* out = (float*)d_out;

    k_init1f<<<(TH_ * T_ + 255) / 256, 256>>>();
    k_init1s<<<(TH_ * TP_ + 255) / 256, 256>>>();
    k_init2s<<<(D_ * KN_ + 255) / 256, 256>>>();
    k_twts<<<(KC_ * D_ + 255) / 256, 256>>>(conv_w);
    k_cvtw<<<(L_ * D_ * HID_ + 255) / 256, 256>>>(w1, w2);
    k_patch_mma<<<dim3(D_ / 128, MP_ / 128), 256>>>(x, conv_b, pos);
    k_cls<<<(B_ * D_) / 256, 256>>>(cls, pos);

    const int MB  = (M_ + 127) / 128;    // 513
    const int MBT = (TH_ + 127) / 128;   // 5
    for (int i = 0; i < L_; i++) {
        k_ln<<<(B_ * T_) / 8, 256>>>(ln1_s + i * D_, ln1_b + i * D_);
        k_dftmma<0><<<dim3(1, MB, 1), 256>>>();
        k_dftmma<1><<<dim3(1, MB, 1), 256>>>();
        k_dftmma<2><<<dim3(1, MBT, B_), 256>>>();
        k_dftmma<3><<<dim3(1, MBT, B_), 256>>>();
        k_tok128<<<dim3((TH_ + 7) / 8, B_), 256>>>();
        k_ln<<<(B_ * T_) / 8, 256>>>(ln2_s + i * D_, ln2_b + i * D_);
        k_ffn_mma<HID_, D_, true ><<<dim3(HID_ / 128, MB), 256>>>(i, b1 + i * HID_);
        k_ffn_mma<D_, HID_, false><<<dim3(D_ / 128, MB), 256>>>(i, b2 + i * D_);
    }

    k_pool<<<B_, D_>>>();
    k_head<<<B_, 256>>>(hls, hlb, hw, hb, out);
}